// round 16
// baseline (speedup 1.0000x reference)
#include <cuda_runtime.h>

// ---------------- problem constants ----------------
#define B_GRAPHS 2048
#define E        256
#define QKV3     768
#define H        4
#define HD       64
#define DM       128
#define DX       128
#define NMAX     (2048*80)
#define LMAX     128
#define CMAX     80
#define KROWS    96            // padded key rows (3*32)
#define KST2     68            // 272B row stride: conflict-free LDS.128

#define GT_THREADS 256

// ---------------- device scratch ----------------
__device__ int   g_is64;
__device__ int   g_counts[B_GRAPHS];
__device__ int   g_offsets[B_GRAPHS];
__device__ int   g_colcnt[LMAX];
__device__ int   g_colprefix[LMAX];
__device__ int   g_rowrank[LMAX * B_GRAPHS];
__device__ int   g_dest[NMAX];
__device__ __align__(16) float g_qkv[(size_t)NMAX * QKV3];
__device__ __align__(16) float g_ctx[(size_t)NMAX * E];
__device__ float g_W2[E * E];
__device__ float g_b2[E];
__device__ __align__(16) uint2 g_wf1[96 * 32 * 32];   // in_proj_w tf32 fragments [nt][kt][lane]
__device__ __align__(16) uint2 g_wf2[32 * 32 * 32];   // W2 tf32 fragments

__device__ __forceinline__ int get_batch(const void* b, int i) {
    if (g_is64) return (int)((const long long*)b)[i];
    return ((const int*)b)[i];
}

__device__ __forceinline__ unsigned f2tf32(float f) {
    unsigned r;
    asm("cvt.rna.tf32.f32 %0, %1;" : "=r"(r) : "f"(f));
    return r;
}

#define MMA_TF32(d, a0, a1, a2, a3, b0, b1)                                   \
  asm volatile("mma.sync.aligned.m16n8k8.row.col.f32.tf32.tf32.f32 "          \
    "{%0,%1,%2,%3}, {%4,%5,%6,%7}, {%8,%9}, {%0,%1,%2,%3};"                   \
    : "+f"((d)[0]), "+f"((d)[1]), "+f"((d)[2]), "+f"((d)[3])                  \
    : "r"(a0), "r"(a1), "r"(a2), "r"(a3), "r"(b0), "r"(b1))

#define CP_ASYNC16(dst, src) \
  asm volatile("cp.async.cg.shared.global [%0], [%1], 16;" :: "r"(dst), "l"(src) : "memory")
#define CP_ASYNC16Z(dst, src, sz) \
  asm volatile("cp.async.cg.shared.global [%0], [%1], 16, %2;" :: "r"(dst), "l"(src), "r"(sz) : "memory")
#define CP_COMMIT() asm volatile("cp.async.commit_group;" ::: "memory")
#define CP_WAIT1()  asm volatile("cp.async.wait_group 1;" ::: "memory")
#define CP_WAIT0()  asm volatile("cp.async.wait_group 0;" ::: "memory")

// ---------------- setup kernels ----------------
__global__ void k_init() {
    int t = blockIdx.x * blockDim.x + threadIdx.x;
    if (t == 0) g_is64 = 1;
    if (t < B_GRAPHS) g_counts[t] = 0;
}

__global__ void k_detect(const void* batch, int N) {
    const int* w = (const int*)batch;
    int t = blockIdx.x * blockDim.x + threadIdx.x;
    for (int j = 1 + 2 * t; j < N; j += 2 * gridDim.x * blockDim.x) {
        if (w[j] != 0) { g_is64 = 0; return; }
    }
}

__global__ void k_counts(const void* batch, int N) {
    int i = blockIdx.x * blockDim.x + threadIdx.x;
    if (i < N) atomicAdd(&g_counts[get_batch(batch, i)], 1);
}

__global__ void k_scan() {
    __shared__ int s[B_GRAPHS];
    int t = threadIdx.x;
    int c0 = g_counts[t], c1 = g_counts[t + 1024];
    s[t] = c0; s[t + 1024] = c1;
    __syncthreads();
    for (int d = 1; d < B_GRAPHS; d <<= 1) {
        int a = (t >= d) ? s[t - d] : 0;
        int b = (t + 1024 >= d) ? s[t + 1024 - d] : 0;
        __syncthreads();
        if (t >= d) s[t] += a;
        if (t + 1024 >= d) s[t + 1024] += b;
        __syncthreads();
    }
    g_offsets[t] = s[t] - c0;
    g_offsets[t + 1024] = s[t + 1024] - c1;
}

__global__ void k_rowrank() {
    int p = blockIdx.x;
    __shared__ int s[B_GRAPHS];
    int t = threadIdx.x;
    int i0 = (g_counts[t] > p) ? 1 : 0;
    int i1 = (g_counts[t + 1024] > p) ? 1 : 0;
    s[t] = i0; s[t + 1024] = i1;
    __syncthreads();
    for (int d = 1; d < B_GRAPHS; d <<= 1) {
        int a = (t >= d) ? s[t - d] : 0;
        int b = (t + 1024 >= d) ? s[t + 1024 - d] : 0;
        __syncthreads();
        if (t >= d) s[t] += a;
        if (t + 1024 >= d) s[t + 1024] += b;
        __syncthreads();
    }
    g_rowrank[p * B_GRAPHS + t] = s[t] - i0;
    g_rowrank[p * B_GRAPHS + t + 1024] = s[t + 1024] - i1;
    if (t == 0) g_colcnt[p] = s[B_GRAPHS - 1];
}

__global__ void k_colprefix() {
    if (threadIdx.x == 0 && blockIdx.x == 0) {
        int run = 0;
        for (int p = 0; p < LMAX; p++) { g_colprefix[p] = run; run += g_colcnt[p]; }
    }
}

__global__ void k_dest(const void* batch, int N) {
    int i = blockIdx.x * blockDim.x + threadIdx.x;
    if (i < N) {
        int b = get_batch(batch, i);
        int p = i - g_offsets[b];
        g_dest[i] = g_colprefix[p] + g_rowrank[p * B_GRAPHS + b];
    }
}

__global__ void k_w2(const float* __restrict__ wout, const float* __restrict__ wo) {
    __shared__ float ws[E];
    int i = blockIdx.x, j = threadIdx.x;
    ws[j] = wout[i * E + j];
    __syncthreads();
    float acc = 0.f;
#pragma unroll 8
    for (int t = 0; t < E; t++) acc += ws[t] * wo[t * E + j];
    g_W2[i * E + j] = acc;
}

__global__ void k_b2(const float* __restrict__ wout, const float* __restrict__ opb,
                     const float* __restrict__ bout) {
    int j = threadIdx.x;
    float acc = bout[j];
    for (int t = 0; t < E; t++) acc += wout[j * E + t] * opb[t];
    g_b2[j] = acc;
}

// ---------------- weight fragment prep ----------------
__global__ void k_wprep1(const float* __restrict__ W) {
    int nt = blockIdx.x;          // 0..95
    int w = threadIdx.x >> 5, lane = threadIdx.x & 31;
    int n = nt * 8 + (lane >> 2);
#pragma unroll
    for (int j = 0; j < 4; j++) {
        int kt = w * 4 + j;
        int k = kt * 8 + (lane & 3);
        uint2 v;
        v.x = f2tf32(W[(size_t)n * E + k]);
        v.y = f2tf32(W[(size_t)n * E + k + 4]);
        g_wf1[(nt * 32 + kt) * 32 + lane] = v;
    }
}

__global__ void k_wprep2() {
    int nt = blockIdx.x;          // 0..31
    int w = threadIdx.x >> 5, lane = threadIdx.x & 31;
    int n = nt * 8 + (lane >> 2);
#pragma unroll
    for (int j = 0; j < 4; j++) {
        int kt = w * 4 + j;
        int k = kt * 8 + (lane & 3);
        uint2 v;
        v.x = f2tf32(g_W2[n * E + k]);
        v.y = f2tf32(g_W2[n * E + k + 4]);
        g_wf2[(nt * 32 + kt) * 32 + lane] = v;
    }
}

// ---------------- GEMM core (R9 proven config) ----------------
__device__ __forceinline__ void issue_B_stage(unsigned* sB, const uint2* __restrict__ wf,
                                              int ps, int tid) {
    int ntb = (ps >> 3) * 32, ktb = (ps & 7) * 4;
    unsigned base = (unsigned)__cvta_generic_to_shared(sB + (ps % 3) * 8192);
#pragma unroll
    for (int j = 0; j < 8; j++) {
        int c = tid + GT_THREADS * j;
        int cc = c & 15;
        int unit = c >> 4;
        int kt_loc = unit >> 5;
        int nt_loc = unit & 31;
        const uint2* src = wf + ((size_t)(ntb + nt_loc) * 32 + ktb + kt_loc) * 32 + cc * 2;
        CP_ASYNC16(base + (unsigned)c * 16, src);
    }
}

template <int NJT>
__device__ __forceinline__ void gemm_body(
    const unsigned* sAf, unsigned* sB, int r0, int N,
    const uint2* __restrict__ wf,
    const float* __restrict__ bias,
    float* __restrict__ outp, int out_ld, const int* __restrict__ dest)
{
    const int tid = threadIdx.x;
    const int lane = tid & 31, warp = tid >> 5;
    const int wm = warp >> 2, wn = warp & 3;
    const int NP = NJT * 8;

    issue_B_stage(sB, wf, 0, tid); CP_COMMIT();
    issue_B_stage(sB, wf, 1, tid); CP_COMMIT();

    int p = 0;
    for (int jt = 0; jt < NJT; jt++) {
        float acc[4][8][4];
#pragma unroll
        for (int mi = 0; mi < 4; mi++)
#pragma unroll
            for (int ni = 0; ni < 8; ni++)
#pragma unroll
                for (int c = 0; c < 4; c++) acc[mi][ni][c] = 0.f;

        for (int it = 0; it < 8; it++, p++) {
            CP_WAIT1();
            __syncthreads();
            if (p + 2 < NP) issue_B_stage(sB, wf, p + 2, tid);
            CP_COMMIT();

            const unsigned* sBc = sB + (p % 3) * 8192;
#pragma unroll
            for (int kt = 0; kt < 4; kt++) {
                int ktg = it * 4 + kt;
                uint4 af[4];
#pragma unroll
                for (int mi = 0; mi < 4; mi++)
                    af[mi] = *(const uint4*)&sAf[((ktg * 8 + wm * 4 + mi) * 32 + lane) * 4];
                uint2 bf[8];
#pragma unroll
                for (int ni = 0; ni < 8; ni++)
                    bf[ni] = *(const uint2*)&sBc[((kt * 32 + wn * 8 + ni) << 6) + lane * 2];
#pragma unroll
                for (int mi = 0; mi < 4; mi++)
#pragma unroll
                    for (int ni = 0; ni < 8; ni++)
                        MMA_TF32(acc[mi][ni], af[mi].x, af[mi].y, af[mi].z, af[mi].w,
                                 bf[ni].x, bf[ni].y);
            }
        }

        int j0 = jt * 256;
#pragma unroll
        for (int mi = 0; mi < 4; mi++) {
            int rowA = r0 + wm * 64 + mi * 16 + (lane >> 2);
            int rowB = rowA + 8;
            bool vA = rowA < N, vB = rowB < N;
            int drA, drB;
            if (dest) { drA = vA ? dest[rowA] : 0; drB = vB ? dest[rowB] : 0; }
            else      { drA = rowA; drB = rowB; }
#pragma unroll
            for (int ni = 0; ni < 8; ni++) {
                int col = j0 + wn * 64 + ni * 8 + (lane & 3) * 2;
                float b0 = bias[col], b1 = bias[col + 1];
                float* a4 = acc[mi][ni];
                if (vA) {
                    float2 v = make_float2(a4[0] + b0, a4[1] + b1);
                    *(float2*)&outp[(size_t)drA * out_ld + col] = v;
                }
                if (vB) {
                    float2 v = make_float2(a4[2] + b0, a4[3] + b1);
                    *(float2*)&outp[(size_t)drB * out_ld + col] = v;
                }
            }
        }
    }
}

// GEMM1: qkv = gather(concat(metal[batch], x)) @ in_proj_w^T + bias
__global__ void __launch_bounds__(GT_THREADS, 1) k_gemm1_tc(
    const float* __restrict__ x, const float* __restrict__ metal,
    const float* __restrict__ bias, const void* __restrict__ batch, int N)
{
    extern __shared__ char smem[];
    unsigned* sAf = (unsigned*)smem;
    unsigned* sB  = sAf + 32768;
    int* srcm     = (int*)(sB + 3 * 8192);

    int tid = threadIdx.x;
    int r0 = blockIdx.x * 128;

    if (tid < 128) {
        int ar = r0 + tid;
        srcm[tid] = (ar < N) ? get_batch(batch, ar) : 0;
    }
    __syncthreads();

    {
        int mt = (tid >> 5) & 7, le = tid & 31;
        int r8 = le >> 2, kk = le & 3;
        int rowA = mt * 16 + r8, rowB = rowA + 8;
        int gA = r0 + rowA, gB = r0 + rowB;
        bool vA = gA < N, vB = gB < N;
        const float* mA = metal + (size_t)srcm[rowA] * DM;
        const float* mB = metal + (size_t)srcm[rowB] * DM;
        const float* xA = x + (size_t)gA * DX;
        const float* xB = x + (size_t)gB * DX;
#pragma unroll 4
        for (int q = 0; q < 32; q++) {
            int k = q * 8 + kk;
            float v0, v1, v2, v3;
            if (q < 16) {
                v0 = vA ? mA[k] : 0.f;
                v1 = vB ? mB[k] : 0.f;
                v2 = vA ? mA[k + 4] : 0.f;
                v3 = vB ? mB[k + 4] : 0.f;
            } else {
                v0 = vA ? xA[k - 128] : 0.f;
                v1 = vB ? xB[k - 128] : 0.f;
                v2 = vA ? xA[k - 124] : 0.f;
                v3 = vB ? xB[k - 124] : 0.f;
            }
            uint4 u;
            u.x = f2tf32(v0); u.y = f2tf32(v1); u.z = f2tf32(v2); u.w = f2tf32(v3);
            *(uint4*)&sAf[(size_t)((q * 8 + mt) * 32 + le) * 4] = u;
        }
    }
    __syncthreads();

    gemm_body<3>(sAf, sB, r0, N, g_wf1, bias, g_qkv, QKV3, nullptr);
}

// GEMM2: out[dest[i]] = ctx[i] @ W2^T + b2
__global__ void __launch_bounds__(GT_THREADS, 1) k_gemm2_tc(float* __restrict__ out, int N)
{
    extern __shared__ char smem[];
    unsigned* sAf = (unsigned*)smem;
    unsigned* sB  = sAf + 32768;

    int tid = threadIdx.x;
    int r0 = blockIdx.x * 128;

    {
        int mt = (tid >> 5) & 7, le = tid & 31;
        int r8 = le >> 2, kk = le & 3;
        int rowA = mt * 16 + r8, rowB = rowA + 8;
        int gA = r0 + rowA, gB = r0 + rowB;
        bool vA = gA < N, vB = gB < N;
        const float* cA = g_ctx + (size_t)gA * E;
        const float* cB = g_ctx + (size_t)gB * E;
#pragma unroll 4
        for (int q = 0; q < 32; q++) {
            int k = q * 8 + kk;
            float v0 = vA ? cA[k] : 0.f;
            float v1 = vB ? cB[k] : 0.f;
            float v2 = vA ? cA[k + 4] : 0.f;
            float v3 = vB ? cB[k + 4] : 0.f;
            uint4 u;
            u.x = f2tf32(v0); u.y = f2tf32(v1); u.z = f2tf32(v2); u.w = f2tf32(v3);
            *(uint4*)&sAf[(size_t)((q * 8 + mt) * 32 + le) * 4] = u;
        }
    }
    __syncthreads();

    gemm_body<1>(sAf, sB, r0, N, g_wf2, g_b2, out, E, g_dest);
}

// ---------------- attention: one block per (graph, head), 4 queries per warp ----------------
// K/V staged via cp.async, bounded to mrows = 32*ceil(cnt/32) rows; all key loops run
// to mcount = ceil(cnt/32) instead of the fixed 3 (eliminates padded-key FFMA work).
__global__ void __launch_bounds__(256) k_attn() {
    extern __shared__ float sm[];
    float* Ks = sm;                        // 96*68
    float* Vs = Ks + KROWS * KST2;         // 96*68
    float* qs = Vs + KROWS * KST2;         // 8*4*64
    float* ps = qs + 8 * 4 * HD;           // 8*4*96

    int g = blockIdx.x >> 2;
    int h = blockIdx.x & 3;
    int cnt = g_counts[g];
    int off = g_offsets[g];
    int mcount = (cnt + 31) >> 5;          // 1..3
    int mrows = mcount << 5;               // 32/64/96

    const float* base = g_qkv + (size_t)off * QKV3;

    // K/V load via cp.async: mrows rows x 16 float4 each for K and V (zfill beyond cnt)
    {
        unsigned ksb = (unsigned)__cvta_generic_to_shared(Ks);
        unsigned vsb = (unsigned)__cvta_generic_to_shared(Vs);
        for (int idx = threadIdx.x; idx < mrows * 16; idx += blockDim.x) {
            int m = idx >> 4, d4 = idx & 15;
            bool valid = m < cnt;
            const float* row = base + (size_t)(valid ? m : 0) * QKV3;
            unsigned soff = (unsigned)(m * KST2 + d4 * 4) * 4;
            int sz = valid ? 16 : 0;
            CP_ASYNC16Z(ksb + soff, row + E + h * HD + d4 * 4, sz);
            CP_ASYNC16Z(vsb + soff, row + 2 * E + h * HD + d4 * 4, sz);
        }
        CP_COMMIT();
        CP_WAIT0();
    }
    __syncthreads();

    int w = threadIdx.x >> 5, lane = threadIdx.x & 31;
    float* qw = qs + w * 4 * HD;
    float* pw = ps + w * 4 * KROWS;

    for (int q0 = w * 4; q0 < cnt; q0 += 32) {
#pragma unroll
        for (int qi = 0; qi < 4; qi++) {
            int qidx = q0 + qi;
            const float* qrow = base + (size_t)((qidx < cnt) ? qidx : q0) * QKV3 + h * HD;
            qw[qi * HD + lane]      = qrow[lane];
            qw[qi * HD + lane + 32] = qrow[lane + 32];
        }
        __syncwarp();

        float s[3][4];
#pragma unroll
        for (int mi = 0; mi < 3; mi++)
#pragma unroll
            for (int qi = 0; qi < 4; qi++) s[mi][qi] = 0.f;

        // scores: d4 outer (Q loads reused), key-groups inner bounded by mcount
#pragma unroll 4
        for (int d4 = 0; d4 < 16; d4++) {
            float4 q0v = *(const float4*)&qw[0 * HD + d4 * 4];
            float4 q1v = *(const float4*)&qw[1 * HD + d4 * 4];
            float4 q2v = *(const float4*)&qw[2 * HD + d4 * 4];
            float4 q3v = *(const float4*)&qw[3 * HD + d4 * 4];
            for (int mi = 0; mi < mcount; mi++) {
                float4 kv = *(const float4*)&Ks[(lane + mi * 32) * KST2 + d4 * 4];
                s[mi][0] += q0v.x * kv.x + q0v.y * kv.y + q0v.z * kv.z + q0v.w * kv.w;
                s[mi][1] += q1v.x * kv.x + q1v.y * kv.y + q1v.z * kv.z + q1v.w * kv.w;
                s[mi][2] += q2v.x * kv.x + q2v.y * kv.y + q2v.z * kv.z + q2v.w * kv.w;
                s[mi][3] += q3v.x * kv.x + q3v.y * kv.y + q3v.z * kv.z + q3v.w * kv.w;
            }
        }

        float mx[4] = {-1e30f, -1e30f, -1e30f, -1e30f};
        for (int mi = 0; mi < mcount; mi++) {
            bool act = (lane + mi * 32) < cnt;
#pragma unroll
            for (int qi = 0; qi < 4; qi++) {
                s[mi][qi] = act ? s[mi][qi] * 0.125f : -1e30f;
                mx[qi] = fmaxf(mx[qi], s[mi][qi]);
            }
        }
#pragma unroll
        for (int qi = 0; qi < 4; qi++)
#pragma unroll
            for (int o = 16; o; o >>= 1)
                mx[qi] = fmaxf(mx[qi], __shfl_xor_sync(0xFFFFFFFFu, mx[qi], o));

        float sum[4] = {0.f, 0.f, 0.f, 0.f};
        for (int mi = 0; mi < mcount; mi++) {
            bool act = (lane + mi * 32) < cnt;
#pragma unroll
            for (int qi = 0; qi < 4; qi++) {
                float e = act ? __expf(s[mi][qi] - mx[qi]) : 0.f;
                s[mi][qi] = e;
                sum[qi] += e;
            }
        }
#pragma unroll
        for (int qi = 0; qi < 4; qi++)
#pragma unroll
            for (int o = 16; o; o >>= 1)
                sum[qi] += __shfl_xor_sync(0xFFFFFFFFu, sum[qi], o);

        float inv[4];
#pragma unroll
        for (int qi = 0; qi < 4; qi++) inv[qi] = 1.f / sum[qi];

        // pw slots in [cnt, 32*mcount) get zeros (act=false path); PV only reads < 4*ceil(cnt/4) <= 32*mcount
        for (int mi = 0; mi < mcount; mi++) {
            int m = lane + mi * 32;
#pragma unroll
            for (int qi = 0; qi < 4; qi++)
                pw[qi * KROWS + m] = s[mi][qi] * inv[qi];
        }
        __syncwarp();

        float a[4][2];
#pragma unroll
        for (int qi = 0; qi < 4; qi++) { a[qi][0] = 0.f; a[qi][1] = 0.f; }
        int mc = (cnt + 3) >> 2;
        for (int c = 0; c < mc; c++) {
            int m0 = c * 4;
            float v00 = Vs[(m0 + 0) * KST2 + lane], v01 = Vs[(m0 + 0) * KST2 + lane + 32];
            float v10 = Vs[(m0 + 1) * KST2 + lane], v11 = Vs[(m0 + 1) * KST2 + lane + 32];
            float v20 = Vs[(m0 + 2) * KST2 + lane], v21 = Vs[(m0 + 2) * KST2 + lane + 32];
            float v30 = Vs[(m0 + 3) * KST2 + lane], v31 = Vs[(m0 + 3) * KST2 + lane + 32];
#pragma unroll
            for (int qi = 0; qi < 4; qi++) {
                float4 pv = *(const float4*)&pw[qi * KROWS + m0];
                a[qi][0] += pv.x * v00 + pv.y * v10 + pv.z * v20 + pv.w * v30;
                a[qi][1] += pv.x * v01 + pv.y * v11 + pv.z * v21 + pv.w * v31;
            }
        }
#pragma unroll
        for (int qi = 0; qi < 4; qi++) {
            int qidx = q0 + qi;
            if (qidx < cnt) {
                float* co = g_ctx + (size_t)(off + qidx) * E + h * HD;
                co[lane]      = a[qi][0];
                co[lane + 32] = a[qi][1];
            }
        }
        __syncwarp();
    }
}

__global__ void k_copytail(float* __restrict__ dst, const float* __restrict__ metal, int n) {
    int i = blockIdx.x * blockDim.x + threadIdx.x;
    if (i < n && i < B_GRAPHS * DM) dst[i] = metal[i];
}

// ---------------- launch ----------------
extern "C" void kernel_launch(void* const* d_in, const int* in_sizes, int n_in,
                              void* d_out, int out_size) {
    const float* x      = (const float*)d_in[0];
    const float* metal  = (const float*)d_in[1];
    const float* in_w   = (const float*)d_in[2];
    const float* in_b   = (const float*)d_in[3];
    const float* outp_w = (const float*)d_in[4];
    const float* outp_b = (const float*)d_in[5];
    const float* w_out  = (const float*)d_in[6];
    const float* b_out  = (const float*)d_in[7];
    const void*  batch  = d_in[8];
    int N = in_sizes[0] / DX;
    float* out = (float*)d_out;

    const int SMEM_G   = 32768 * 4 + 3 * 8192 * 4 + 512;
    const int SMEM_ATT = (2 * KROWS * KST2 + 8 * 4 * HD + 8 * 4 * KROWS) * 4;

    cudaFuncSetAttribute(k_gemm1_tc, cudaFuncAttributeMaxDynamicSharedMemorySize, SMEM_G);
    cudaFuncSetAttribute(k_gemm2_tc, cudaFuncAttributeMaxDynamicSharedMemorySize, SMEM_G);
    cudaFuncSetAttribute(k_attn,     cudaFuncAttributeMaxDynamicSharedMemorySize, SMEM_ATT);

    k_init<<<(B_GRAPHS + 255) / 256, 256>>>();
    k_detect<<<64, 256>>>(batch, N);
    k_wprep1<<<96, 256>>>(in_w);

    int nblk = (N + 127) / 128;
    k_gemm1_tc<<<nblk, GT_THREADS, SMEM_G>>>(x, metal, in_b, batch, N);

    k_counts<<<(N + 255) / 256, 256>>>(batch, N);
    k_scan<<<1, 1024>>>();
    k_rowrank<<<LMAX, 1024>>>();
    k_colprefix<<<1, 32>>>();
    k_dest<<<(N + 255) / 256, 256>>>(batch, N);
    k_w2<<<E, E>>>(w_out, outp_w);
    k_b2<<<1, E>>>(w_out, outp_b, b_out);
    k_wprep2<<<32, 256>>>();

    k_attn<<<B_GRAPHS * H, 256, SMEM_ATT>>>();

    k_gemm2_tc<<<nblk, GT_THREADS, SMEM_G>>>(out, N);

    long long tail = (long long)out_size - (long long)N * E;
    if (tail > 0) {
        k_copytail<<<((int)tail + 255) / 256, 256>>>(out + (size_t)N * E, metal, (int)tail);
    }
}

// round 17
// speedup vs baseline: 1.2905x; 1.2905x over previous
#include <cuda_runtime.h>

// ---------------- problem constants ----------------
#define B_GRAPHS 2048
#define E        256
#define QKV3     768
#define H        4
#define HD       64
#define DM       128
#define DX       128
#define NMAX     (2048*80)
#define LMAX     128
#define CMAX     80
#define KROWS    96            // padded key rows (3*32)
#define KST2     68            // 272B row stride: conflict-free LDS.128

#define GT_THREADS 256

// ---------------- device scratch ----------------
__device__ int   g_is64;
__device__ int   g_counts[B_GRAPHS];
__device__ int   g_offsets[B_GRAPHS];
__device__ int   g_colcnt[LMAX];
__device__ int   g_colprefix[LMAX];
__device__ int   g_rowrank[LMAX * B_GRAPHS];
__device__ int   g_dest[NMAX];
__device__ __align__(16) float g_qkv[(size_t)NMAX * QKV3];
__device__ __align__(16) float g_ctx[(size_t)NMAX * E];
__device__ float g_W2[E * E];
__device__ float g_b2[E];
__device__ __align__(16) uint2 g_wf1[96 * 32 * 32];
__device__ __align__(16) uint2 g_wf2[32 * 32 * 32];

__device__ __forceinline__ int get_batch(const void* b, int i) {
    if (g_is64) return (int)((const long long*)b)[i];
    return ((const int*)b)[i];
}

__device__ __forceinline__ unsigned f2tf32(float f) {
    unsigned r;
    asm("cvt.rna.tf32.f32 %0, %1;" : "=r"(r) : "f"(f));
    return r;
}

#define MMA_TF32(d, a0, a1, a2, a3, b0, b1)                                   \
  asm volatile("mma.sync.aligned.m16n8k8.row.col.f32.tf32.tf32.f32 "          \
    "{%0,%1,%2,%3}, {%4,%5,%6,%7}, {%8,%9}, {%0,%1,%2,%3};"                   \
    : "+f"((d)[0]), "+f"((d)[1]), "+f"((d)[2]), "+f"((d)[3])                  \
    : "r"(a0), "r"(a1), "r"(a2), "r"(a3), "r"(b0), "r"(b1))

#define CP_ASYNC16(dst, src) \
  asm volatile("cp.async.cg.shared.global [%0], [%1], 16;" :: "r"(dst), "l"(src) : "memory")
#define CP_ASYNC16Z(dst, src, sz) \
  asm volatile("cp.async.cg.shared.global [%0], [%1], 16, %2;" :: "r"(dst), "l"(src), "r"(sz) : "memory")
#define CP_COMMIT() asm volatile("cp.async.commit_group;" ::: "memory")
#define CP_WAIT1()  asm volatile("cp.async.wait_group 1;" ::: "memory")
#define CP_WAIT0()  asm volatile("cp.async.wait_group 0;" ::: "memory")

// ---------------- setup kernels ----------------
__global__ void k_init() {
    int t = blockIdx.x * blockDim.x + threadIdx.x;
    if (t == 0) g_is64 = 1;
    if (t < B_GRAPHS) g_counts[t] = 0;
}

__global__ void k_detect(const void* batch, int N) {
    const int* w = (const int*)batch;
    int t = blockIdx.x * blockDim.x + threadIdx.x;
    for (int j = 1 + 2 * t; j < N; j += 2 * gridDim.x * blockDim.x) {
        if (w[j] != 0) { g_is64 = 0; return; }
    }
}

__global__ void k_counts(const void* batch, int N) {
    int i = blockIdx.x * blockDim.x + threadIdx.x;
    if (i < N) atomicAdd(&g_counts[get_batch(batch, i)], 1);
}

__global__ void k_scan() {
    __shared__ int s[B_GRAPHS];
    int t = threadIdx.x;
    int c0 = g_counts[t], c1 = g_counts[t + 1024];
    s[t] = c0; s[t + 1024] = c1;
    __syncthreads();
    for (int d = 1; d < B_GRAPHS; d <<= 1) {
        int a = (t >= d) ? s[t - d] : 0;
        int b = (t + 1024 >= d) ? s[t + 1024 - d] : 0;
        __syncthreads();
        if (t >= d) s[t] += a;
        if (t + 1024 >= d) s[t + 1024] += b;
        __syncthreads();
    }
    g_offsets[t] = s[t] - c0;
    g_offsets[t + 1024] = s[t + 1024] - c1;
}

__global__ void k_rowrank() {
    int p = blockIdx.x;
    __shared__ int s[B_GRAPHS];
    int t = threadIdx.x;
    int i0 = (g_counts[t] > p) ? 1 : 0;
    int i1 = (g_counts[t + 1024] > p) ? 1 : 0;
    s[t] = i0; s[t + 1024] = i1;
    __syncthreads();
    for (int d = 1; d < B_GRAPHS; d <<= 1) {
        int a = (t >= d) ? s[t - d] : 0;
        int b = (t + 1024 >= d) ? s[t + 1024 - d] : 0;
        __syncthreads();
        if (t >= d) s[t] += a;
        if (t + 1024 >= d) s[t + 1024] += b;
        __syncthreads();
    }
    g_rowrank[p * B_GRAPHS + t] = s[t] - i0;
    g_rowrank[p * B_GRAPHS + t + 1024] = s[t + 1024] - i1;
    if (t == 0) g_colcnt[p] = s[B_GRAPHS - 1];
}

__global__ void k_colprefix() {
    if (threadIdx.x == 0 && blockIdx.x == 0) {
        int run = 0;
        for (int p = 0; p < LMAX; p++) { g_colprefix[p] = run; run += g_colcnt[p]; }
    }
}

__global__ void k_dest(const void* batch, int N) {
    int i = blockIdx.x * blockDim.x + threadIdx.x;
    if (i < N) {
        int b = get_batch(batch, i);
        int p = i - g_offsets[b];
        g_dest[i] = g_colprefix[p] + g_rowrank[p * B_GRAPHS + b];
    }
}

__global__ void k_w2(const float* __restrict__ wout, const float* __restrict__ wo) {
    __shared__ float ws[E];
    int i = blockIdx.x, j = threadIdx.x;
    ws[j] = wout[i * E + j];
    __syncthreads();
    float acc = 0.f;
#pragma unroll 8
    for (int t = 0; t < E; t++) acc += ws[t] * wo[t * E + j];
    g_W2[i * E + j] = acc;
}

__global__ void k_b2(const float* __restrict__ wout, const float* __restrict__ opb,
                     const float* __restrict__ bout) {
    int j = threadIdx.x;
    float acc = bout[j];
    for (int t = 0; t < E; t++) acc += wout[j * E + t] * opb[t];
    g_b2[j] = acc;
}

// ---------------- weight fragment prep ----------------
__global__ void k_wprep1(const float* __restrict__ W) {
    int nt = blockIdx.x;
    int w = threadIdx.x >> 5, lane = threadIdx.x & 31;
    int n = nt * 8 + (lane >> 2);
#pragma unroll
    for (int j = 0; j < 4; j++) {
        int kt = w * 4 + j;
        int k = kt * 8 + (lane & 3);
        uint2 v;
        v.x = f2tf32(W[(size_t)n * E + k]);
        v.y = f2tf32(W[(size_t)n * E + k + 4]);
        g_wf1[(nt * 32 + kt) * 32 + lane] = v;
    }
}

__global__ void k_wprep2() {
    int nt = blockIdx.x;
    int w = threadIdx.x >> 5, lane = threadIdx.x & 31;
    int n = nt * 8 + (lane >> 2);
#pragma unroll
    for (int j = 0; j < 4; j++) {
        int kt = w * 4 + j;
        int k = kt * 8 + (lane & 3);
        uint2 v;
        v.x = f2tf32(g_W2[n * E + k]);
        v.y = f2tf32(g_W2[n * E + k + 4]);
        g_wf2[(nt * 32 + kt) * 32 + lane] = v;
    }
}

// ---------------- GEMM core (R9 proven config) ----------------
__device__ __forceinline__ void issue_B_stage(unsigned* sB, const uint2* __restrict__ wf,
                                              int ps, int tid) {
    int ntb = (ps >> 3) * 32, ktb = (ps & 7) * 4;
    unsigned base = (unsigned)__cvta_generic_to_shared(sB + (ps % 3) * 8192);
#pragma unroll
    for (int j = 0; j < 8; j++) {
        int c = tid + GT_THREADS * j;
        int cc = c & 15;
        int unit = c >> 4;
        int kt_loc = unit >> 5;
        int nt_loc = unit & 31;
        const uint2* src = wf + ((size_t)(ntb + nt_loc) * 32 + ktb + kt_loc) * 32 + cc * 2;
        CP_ASYNC16(base + (unsigned)c * 16, src);
    }
}

template <int NJT>
__device__ __forceinline__ void gemm_body(
    const unsigned* sAf, unsigned* sB, int r0, int N,
    const uint2* __restrict__ wf,
    const float* __restrict__ bias,
    float* __restrict__ outp, int out_ld, const int* __restrict__ dest)
{
    const int tid = threadIdx.x;
    const int lane = tid & 31, warp = tid >> 5;
    const int wm = warp >> 2, wn = warp & 3;
    const int NP = NJT * 8;

    issue_B_stage(sB, wf, 0, tid); CP_COMMIT();
    issue_B_stage(sB, wf, 1, tid); CP_COMMIT();

    int p = 0;
    for (int jt = 0; jt < NJT; jt++) {
        float acc[4][8][4];
#pragma unroll
        for (int mi = 0; mi < 4; mi++)
#pragma unroll
            for (int ni = 0; ni < 8; ni++)
#pragma unroll
                for (int c = 0; c < 4; c++) acc[mi][ni][c] = 0.f;

        for (int it = 0; it < 8; it++, p++) {
            CP_WAIT1();
            __syncthreads();
            if (p + 2 < NP) issue_B_stage(sB, wf, p + 2, tid);
            CP_COMMIT();

            const unsigned* sBc = sB + (p % 3) * 8192;
#pragma unroll
            for (int kt = 0; kt < 4; kt++) {
                int ktg = it * 4 + kt;
                uint4 af[4];
#pragma unroll
                for (int mi = 0; mi < 4; mi++)
                    af[mi] = *(const uint4*)&sAf[((ktg * 8 + wm * 4 + mi) * 32 + lane) * 4];
                uint2 bf[8];
#pragma unroll
                for (int ni = 0; ni < 8; ni++)
                    bf[ni] = *(const uint2*)&sBc[((kt * 32 + wn * 8 + ni) << 6) + lane * 2];
#pragma unroll
                for (int mi = 0; mi < 4; mi++)
#pragma unroll
                    for (int ni = 0; ni < 8; ni++)
                        MMA_TF32(acc[mi][ni], af[mi].x, af[mi].y, af[mi].z, af[mi].w,
                                 bf[ni].x, bf[ni].y);
            }
        }

        int j0 = jt * 256;
#pragma unroll
        for (int mi = 0; mi < 4; mi++) {
            int rowA = r0 + wm * 64 + mi * 16 + (lane >> 2);
            int rowB = rowA + 8;
            bool vA = rowA < N, vB = rowB < N;
            int drA, drB;
            if (dest) { drA = vA ? dest[rowA] : 0; drB = vB ? dest[rowB] : 0; }
            else      { drA = rowA; drB = rowB; }
#pragma unroll
            for (int ni = 0; ni < 8; ni++) {
                int col = j0 + wn * 64 + ni * 8 + (lane & 3) * 2;
                float b0 = bias[col], b1 = bias[col + 1];
                float* a4 = acc[mi][ni];
                if (vA) {
                    float2 v = make_float2(a4[0] + b0, a4[1] + b1);
                    *(float2*)&outp[(size_t)drA * out_ld + col] = v;
                }
                if (vB) {
                    float2 v = make_float2(a4[2] + b0, a4[3] + b1);
                    *(float2*)&outp[(size_t)drB * out_ld + col] = v;
                }
            }
        }
    }
}

// GEMM1: qkv = gather(concat(metal[batch], x)) @ in_proj_w^T + bias
__global__ void __launch_bounds__(GT_THREADS, 1) k_gemm1_tc(
    const float* __restrict__ x, const float* __restrict__ metal,
    const float* __restrict__ bias, const void* __restrict__ batch, int N)
{
    extern __shared__ char smem[];
    unsigned* sAf = (unsigned*)smem;
    unsigned* sB  = sAf + 32768;
    int* srcm     = (int*)(sB + 3 * 8192);

    int tid = threadIdx.x;
    int r0 = blockIdx.x * 128;

    if (tid < 128) {
        int ar = r0 + tid;
        srcm[tid] = (ar < N) ? get_batch(batch, ar) : 0;
    }
    __syncthreads();

    {
        int mt = (tid >> 5) & 7, le = tid & 31;
        int r8 = le >> 2, kk = le & 3;
        int rowA = mt * 16 + r8, rowB = rowA + 8;
        int gA = r0 + rowA, gB = r0 + rowB;
        bool vA = gA < N, vB = gB < N;
        const float* mA = metal + (size_t)srcm[rowA] * DM;
        const float* mB = metal + (size_t)srcm[rowB] * DM;
        const float* xA = x + (size_t)gA * DX;
        const float* xB = x + (size_t)gB * DX;
#pragma unroll 4
        for (int q = 0; q < 32; q++) {
            int k = q * 8 + kk;
            float v0, v1, v2, v3;
            if (q < 16) {
                v0 = vA ? mA[k] : 0.f;
                v1 = vB ? mB[k] : 0.f;
                v2 = vA ? mA[k + 4] : 0.f;
                v3 = vB ? mB[k + 4] : 0.f;
            } else {
                v0 = vA ? xA[k - 128] : 0.f;
                v1 = vB ? xB[k - 128] : 0.f;
                v2 = vA ? xA[k - 124] : 0.f;
                v3 = vB ? xB[k - 124] : 0.f;
            }
            uint4 u;
            u.x = f2tf32(v0); u.y = f2tf32(v1); u.z = f2tf32(v2); u.w = f2tf32(v3);
            *(uint4*)&sAf[(size_t)((q * 8 + mt) * 32 + le) * 4] = u;
        }
    }
    __syncthreads();

    gemm_body<3>(sAf, sB, r0, N, g_wf1, bias, g_qkv, QKV3, nullptr);
}

// GEMM2: out[dest[i]] = ctx[i] @ W2^T + b2
__global__ void __launch_bounds__(GT_THREADS, 1) k_gemm2_tc(float* __restrict__ out, int N)
{
    extern __shared__ char smem[];
    unsigned* sAf = (unsigned*)smem;
    unsigned* sB  = sAf + 32768;

    int tid = threadIdx.x;
    int r0 = blockIdx.x * 128;

    {
        int mt = (tid >> 5) & 7, le = tid & 31;
        int r8 = le >> 2, kk = le & 3;
        int rowA = mt * 16 + r8, rowB = rowA + 8;
        int gA = r0 + rowA, gB = r0 + rowB;
        bool vA = gA < N, vB = gB < N;
        const float* cA = g_ctx + (size_t)gA * E;
        const float* cB = g_ctx + (size_t)gB * E;
#pragma unroll 4
        for (int q = 0; q < 32; q++) {
            int k = q * 8 + kk;
            float v0 = vA ? cA[k] : 0.f;
            float v1 = vB ? cB[k] : 0.f;
            float v2 = vA ? cA[k + 4] : 0.f;
            float v3 = vB ? cB[k + 4] : 0.f;
            uint4 u;
            u.x = f2tf32(v0); u.y = f2tf32(v1); u.z = f2tf32(v2); u.w = f2tf32(v3);
            *(uint4*)&sAf[(size_t)((q * 8 + mt) * 32 + le) * 4] = u;
        }
    }
    __syncthreads();

    gemm_body<1>(sAf, sB, r0, N, g_wf2, g_b2, out, E, g_dest);
}

// ---------------- attention: compile-time MC variants ----------------
// Per-warp body templated on MC = ceil(cnt/32) so every loop is fully
// unrolled and s[MC][4] stays in registers (R16's runtime bound caused
// local-memory spills). pw slots < 32*MC are always written (zeros beyond
// cnt); PV reads < 4*ceil(cnt/4) <= 32*MC.
template <int MC>
__device__ __forceinline__ void attn_warp_body(
    const float* __restrict__ base, float* Ks, float* Vs, float* qw, float* pw,
    int cnt, int off, int h, int w, int lane)
{
    for (int q0 = w * 4; q0 < cnt; q0 += 32) {
#pragma unroll
        for (int qi = 0; qi < 4; qi++) {
            int qidx = q0 + qi;
            const float* qrow = base + (size_t)((qidx < cnt) ? qidx : q0) * QKV3 + h * HD;
            qw[qi * HD + lane]      = qrow[lane];
            qw[qi * HD + lane + 32] = qrow[lane + 32];
        }
        __syncwarp();

        float s[MC][4];
#pragma unroll
        for (int mi = 0; mi < MC; mi++)
#pragma unroll
            for (int qi = 0; qi < 4; qi++) s[mi][qi] = 0.f;

#pragma unroll 4
        for (int d4 = 0; d4 < 16; d4++) {
            float4 q0v = *(const float4*)&qw[0 * HD + d4 * 4];
            float4 q1v = *(const float4*)&qw[1 * HD + d4 * 4];
            float4 q2v = *(const float4*)&qw[2 * HD + d4 * 4];
            float4 q3v = *(const float4*)&qw[3 * HD + d4 * 4];
#pragma unroll
            for (int mi = 0; mi < MC; mi++) {
                float4 kv = *(const float4*)&Ks[(lane + mi * 32) * KST2 + d4 * 4];
                s[mi][0] += q0v.x * kv.x + q0v.y * kv.y + q0v.z * kv.z + q0v.w * kv.w;
                s[mi][1] += q1v.x * kv.x + q1v.y * kv.y + q1v.z * kv.z + q1v.w * kv.w;
                s[mi][2] += q2v.x * kv.x + q2v.y * kv.y + q2v.z * kv.z + q2v.w * kv.w;
                s[mi][3] += q3v.x * kv.x + q3v.y * kv.y + q3v.z * kv.z + q3v.w * kv.w;
            }
        }

        float mx[4] = {-1e30f, -1e30f, -1e30f, -1e30f};
#pragma unroll
        for (int mi = 0; mi < MC; mi++) {
            bool act = (lane + mi * 32) < cnt;
#pragma unroll
            for (int qi = 0; qi < 4; qi++) {
                s[mi][qi] = act ? s[mi][qi] * 0.125f : -1e30f;
                mx[qi] = fmaxf(mx[qi], s[mi][qi]);
            }
        }
#pragma unroll
        for (int qi = 0; qi < 4; qi++)
#pragma unroll
            for (int o = 16; o; o >>= 1)
                mx[qi] = fmaxf(mx[qi], __shfl_xor_sync(0xFFFFFFFFu, mx[qi], o));

        float sum[4] = {0.f, 0.f, 0.f, 0.f};
#pragma unroll
        for (int mi = 0; mi < MC; mi++) {
            bool act = (lane + mi * 32) < cnt;
#pragma unroll
            for (int qi = 0; qi < 4; qi++) {
                float e = act ? __expf(s[mi][qi] - mx[qi]) : 0.f;
                s[mi][qi] = e;
                sum[qi] += e;
            }
        }
#pragma unroll
        for (int qi = 0; qi < 4; qi++)
#pragma unroll
            for (int o = 16; o; o >>= 1)
                sum[qi] += __shfl_xor_sync(0xFFFFFFFFu, sum[qi], o);

        float inv[4];
#pragma unroll
        for (int qi = 0; qi < 4; qi++) inv[qi] = 1.f / sum[qi];

#pragma unroll
        for (int mi = 0; mi < MC; mi++) {
            int m = lane + mi * 32;
#pragma unroll
            for (int qi = 0; qi < 4; qi++)
                pw[qi * KROWS + m] = s[mi][qi] * inv[qi];
        }
        __syncwarp();

        float a[4][2];
#pragma unroll
        for (int qi = 0; qi < 4; qi++) { a[qi][0] = 0.f; a[qi][1] = 0.f; }
        int mc4 = (cnt + 3) >> 2;
        for (int c = 0; c < mc4; c++) {
            int m0 = c * 4;
            float v00 = Vs[(m0 + 0) * KST2 + lane], v01 = Vs[(m0 + 0) * KST2 + lane + 32];
            float v10 = Vs[(m0 + 1) * KST2 + lane], v11 = Vs[(m0 + 1) * KST2 + lane + 32];
            float v20 = Vs[(m0 + 2) * KST2 + lane], v21 = Vs[(m0 + 2) * KST2 + lane + 32];
            float v30 = Vs[(m0 + 3) * KST2 + lane], v31 = Vs[(m0 + 3) * KST2 + lane + 32];
#pragma unroll
            for (int qi = 0; qi < 4; qi++) {
                float4 pv = *(const float4*)&pw[qi * KROWS + m0];
                a[qi][0] += pv.x * v00 + pv.y * v10 + pv.z * v20 + pv.w * v30;
                a[qi][1] += pv.x * v01 + pv.y * v11 + pv.z * v21 + pv.w * v31;
            }
        }
#pragma unroll
        for (int qi = 0; qi < 4; qi++) {
            int qidx = q0 + qi;
            if (qidx < cnt) {
                float* co = g_ctx + (size_t)(off + qidx) * E + h * HD;
                co[lane]      = a[qi][0];
                co[lane + 32] = a[qi][1];
            }
        }
        __syncwarp();
    }
}

__global__ void __launch_bounds__(256) k_attn() {
    extern __shared__ float sm[];
    float* Ks = sm;                        // 96*68
    float* Vs = Ks + KROWS * KST2;         // 96*68
    float* qs = Vs + KROWS * KST2;         // 8*4*64
    float* ps = qs + 8 * 4 * HD;           // 8*4*96

    int g = blockIdx.x >> 2;
    int h = blockIdx.x & 3;
    int cnt = g_counts[g];
    int off = g_offsets[g];
    int mcount = (cnt + 31) >> 5;          // 1..3
    int mrows = mcount << 5;

    const float* base = g_qkv + (size_t)off * QKV3;

    // K/V load via cp.async (zfill beyond cnt), bounded to mrows
    {
        unsigned ksb = (unsigned)__cvta_generic_to_shared(Ks);
        unsigned vsb = (unsigned)__cvta_generic_to_shared(Vs);
        for (int idx = threadIdx.x; idx < mrows * 16; idx += blockDim.x) {
            int m = idx >> 4, d4 = idx & 15;
            bool valid = m < cnt;
            const float* row = base + (size_t)(valid ? m : 0) * QKV3;
            unsigned soff = (unsigned)(m * KST2 + d4 * 4) * 4;
            int sz = valid ? 16 : 0;
            CP_ASYNC16Z(ksb + soff, row + E + h * HD + d4 * 4, sz);
            CP_ASYNC16Z(vsb + soff, row + 2 * E + h * HD + d4 * 4, sz);
        }
        CP_COMMIT();
        CP_WAIT0();
    }
    __syncthreads();

    int w = threadIdx.x >> 5, lane = threadIdx.x & 31;
    float* qw = qs + w * 4 * HD;
    float* pw = ps + w * 4 * KROWS;

    switch (mcount) {
        case 1: attn_warp_body<1>(base, Ks, Vs, qw, pw, cnt, off, h, w, lane); break;
        case 2: attn_warp_body<2>(base, Ks, Vs, qw, pw, cnt, off, h, w, lane); break;
        default: attn_warp_body<3>(base, Ks, Vs, qw, pw, cnt, off, h, w, lane); break;
    }
}

__global__ void k_copytail(float* __restrict__ dst, const float* __restrict__ metal, int n) {
    int i = blockIdx.x * blockDim.x + threadIdx.x;
    if (i < n && i < B_GRAPHS * DM) dst[i] = metal[i];
}

// ---------------- launch ----------------
extern "C" void kernel_launch(void* const* d_in, const int* in_sizes, int n_in,
                              void* d_out, int out_size) {
    const float* x      = (const float*)d_in[0];
    const float* metal  = (const float*)d_in[1];
    const float* in_w   = (const float*)d_in[2];
    const float* in_b   = (const float*)d_in[3];
    const float* outp_w = (const float*)d_in[4];
    const float* outp_b = (const float*)d_in[5];
    const float* w_out  = (const float*)d_in[6];
    const float* b_out  = (const float*)d_in[7];
    const void*  batch  = d_in[8];
    int N = in_sizes[0] / DX;
    float* out = (float*)d_out;

    const int SMEM_G   = 32768 * 4 + 3 * 8192 * 4 + 512;
    const int SMEM_ATT = (2 * KROWS * KST2 + 8 * 4 * HD + 8 * 4 * KROWS) * 4;

    cudaFuncSetAttribute(k_gemm1_tc, cudaFuncAttributeMaxDynamicSharedMemorySize, SMEM_G);
    cudaFuncSetAttribute(k_gemm2_tc, cudaFuncAttributeMaxDynamicSharedMemorySize, SMEM_G);
    cudaFuncSetAttribute(k_attn,     cudaFuncAttributeMaxDynamicSharedMemorySize, SMEM_ATT);

    k_init<<<(B_GRAPHS + 255) / 256, 256>>>();
    k_detect<<<64, 256>>>(batch, N);
    k_wprep1<<<96, 256>>>(in_w);

    int nblk = (N + 127) / 128;
    k_gemm1_tc<<<nblk, GT_THREADS, SMEM_G>>>(x, metal, in_b, batch, N);

    k_counts<<<(N + 255) / 256, 256>>>(batch, N);
    k_scan<<<1, 1024>>>();
    k_rowrank<<<LMAX, 1024>>>();
    k_colprefix<<<1, 32>>>();
    k_dest<<<(N + 255) / 256, 256>>>(batch, N);
    k_w2<<<E, E>>>(w_out, outp_w);
    k_b2<<<1, E>>>(w_out, outp_b, b_out);
    k_wprep2<<<32, 256>>>();

    k_attn<<<B_GRAPHS * H, 256, SMEM_ATT>>>();

    k_gemm2_tc<<<nblk, GT_THREADS, SMEM_G>>>(out, N);

    long long tail = (long long)out_size - (long long)N * E;
    if (tail > 0) {
        k_copytail<<<((int)tail + 255) / 256, 256>>>(out + (size_t)N * E, metal, (int)tail);
    }
}